// round 12
// baseline (speedup 1.0000x reference)
#include <cuda_runtime.h>
#include <cuda_bf16.h>
#include <cstdint>

// ===========================================================================
// Goal_Conditioned_Policies forward, persistent-CTA conv + warp-per-sample MLP.
// K1: one CTA per SM (1024 thr), grid-strides over samples. Weights/halos
//     resident in smem; conv2 software-pipelined with DEPTH-2 prefetch
//     (triple-buffered fragments).
// K2: warp-per-sample MLP + C matvec + softmax in registers via shfl.
// ===========================================================================

#define NTHREADS  1024
#define NVAR      50
#define B_SAMPLES 4096

// ---- K1 smem byte offsets ----
#define XQ_OFF   0u            // [4 pyx][33][33][16B] = 69,696
#define P_OFF    69696u        // [4 pyx][4 g][17][17][16B] = 73,984
#define B1_OFF   143680u       // conv1 weights [80 k][80 B rows] = 6,400
#define B2_OFF   150080u       // conv2 weights [288 k][144 B rows] = 41,472
#define VEC_OFF  191552u
#define SMEM_BYTES 196096u

#define XQ_REG 17424u          // 33*33*16
#define P_REG  4624u           // 17*17*16

// vec float indices
#define V_B1S  0
#define V_B2S  32
#define V_PP   96        // pool partials [32 warps][32]

__device__ __forceinline__ uint32_t smem_u32(const void* p) {
    uint32_t a;
    asm("{ .reg .u64 t; cvta.to.shared.u64 t, %1; cvt.u32.u64 %0, t; }" : "=r"(a) : "l"(p));
    return a;
}
__device__ __forceinline__ void ldsm_x4(uint32_t* r, uint32_t addr) {
    asm volatile("ldmatrix.sync.aligned.m8n8.x4.shared.b16 {%0,%1,%2,%3}, [%4];"
        : "=r"(r[0]), "=r"(r[1]), "=r"(r[2]), "=r"(r[3]) : "r"(addr));
}
__device__ __forceinline__ void ldsm_x4_t(uint32_t* r, uint32_t addr) {
    asm volatile("ldmatrix.sync.aligned.m8n8.x4.trans.shared.b16 {%0,%1,%2,%3}, [%4];"
        : "=r"(r[0]), "=r"(r[1]), "=r"(r[2]), "=r"(r[3]) : "r"(addr));
}
__device__ __forceinline__ void mma16816(float* d, const uint32_t* a, const uint32_t* b) {
    asm volatile(
        "mma.sync.aligned.m16n8k16.row.col.f32.bf16.bf16.f32 "
        "{%0,%1,%2,%3}, {%4,%5,%6,%7}, {%8,%9}, {%0,%1,%2,%3};"
        : "+f"(d[0]), "+f"(d[1]), "+f"(d[2]), "+f"(d[3])
        : "r"(a[0]), "r"(a[1]), "r"(a[2]), "r"(a[3]), "r"(b[0]), "r"(b[1]));
}
__device__ __forceinline__ uint32_t pack_bf16x2(float lo, float hi) {
    uint32_t r;
    asm("cvt.rn.bf16x2.f32 %0, %1, %2;" : "=r"(r) : "f"(hi), "f"(lo));
    return r;
}

// --- global scratch (static device arrays; rebuilt deterministically) ---
__device__ __align__(16) __nv_bfloat16 g_B1[80 * 40];
__device__ __align__(16) __nv_bfloat16 g_B2[288 * 72];
__device__ __align__(16) float g_pool[B_SAMPLES * 64];

__global__ void w_prep_kernel(const float* __restrict__ w1, const float* __restrict__ w2) {
    int i = blockIdx.x * blockDim.x + threadIdx.x;
    if (i < 80 * 40) {
        int kk = i / 40, slot = i - kk * 40;
        int tap = kk >> 3, j = kk & 7;
        float v = 0.f;
        if (slot < 32 && j < 3 && kk < 72)
            v = w1[slot * 27 + j * 9 + tap];    // w1[oc][ic=j][tap]
        g_B1[i] = __float2bfloat16(v);
    }
    int i2 = i - 80 * 40;
    if (i2 >= 0 && i2 < 288 * 72) {
        int kk = i2 / 72, slot = i2 - kk * 72;
        int tap = kk >> 5, ic = kk & 31;
        float v = (slot < 64) ? w2[(slot * 32 + ic) * 9 + tap] : 0.f;
        g_B2[i2] = __float2bfloat16(v);
    }
}

// Stage sample's x into XQ (lower 8B of each interior pixel cell; upper 8B of
// every cell is zeroed once at setup and never overwritten).
__device__ __forceinline__ void stage_xq(char* smc, int tid, const float* __restrict__ x, int s) {
    const float* xb = x + (size_t)s * 12288;
    #pragma unroll
    for (int it = 0; it < 4; it++) {
        int i = it * NTHREADS + tid;            // pixel index 0..4095
        float v0 = xb[i];
        float v1 = xb[4096 + i];
        float v2 = xb[8192 + i];
        uint2 q;
        q.x = pack_bf16x2(v0, v1);
        q.y = pack_bf16x2(v2, 0.f);
        int Y = (i >> 6) + 1, X = (i & 63) + 1;
        uint32_t off = XQ_OFF + (uint32_t)((Y & 1) * 2 + (X & 1)) * XQ_REG
                     + (uint32_t)((Y >> 1) * 33 + (X >> 1)) * 16u;
        *(uint2*)(smc + off) = q;
    }
}

// ===========================================================================
// K1: persistent convs + pool (1024 threads, 32 warps, 1 CTA/SM)
// ===========================================================================
__global__ __launch_bounds__(NTHREADS, 1)
void gcp_conv_kernel(const float* __restrict__ x,
                     const float* __restrict__ b1, const float* __restrict__ b2)
{
    extern __shared__ char smc[];
    const uint32_t smaddr = smem_u32(smc);
    const int tid  = threadIdx.x;
    const int wrp  = tid >> 5;
    const int lane = tid & 31;
    float* vec = (float*)(smc + VEC_OFF);

    // ---- one-time setup: zero FULL XQ (pads + halos), P halos, B1/B2, biases ----
    {
        uint4 z = make_uint4(0, 0, 0, 0);
        for (int i = tid; i < 4356; i += NTHREADS)      // all of XQ (69,696 B)
            ((uint4*)(smc + XQ_OFF))[i] = z;
        for (int i = tid; i < 544; i += NTHREADS) {
            int c = i / 34, r = i - c * 34;
            int pyx = c >> 2, g = c & 3;
            int py = pyx >> 1, px = pyx & 1;
            int iy_h = (py == 0) ? 0 : 16;
            int ix_h = (px == 0) ? 0 : 16;
            int iy, ix;
            if (r < 17) { iy = iy_h; ix = r; }
            else        { iy = r - 17; ix = ix_h; }
            *(uint4*)(smc + P_OFF + (uint32_t)(pyx * 4 + g) * P_REG
                      + (uint32_t)(iy * 17 + ix) * 16u) = z;
        }
        const uint4* gb1 = (const uint4*)g_B1;
        for (int i = tid; i < 400; i += NTHREADS)
            ((uint4*)(smc + B1_OFF))[i] = gb1[i];
        const uint4* gb2 = (const uint4*)g_B2;
        for (int i = tid; i < 2592; i += NTHREADS)
            ((uint4*)(smc + B2_OFF))[i] = gb2[i];
        if (tid < 32) vec[V_B1S + tid] = b1[tid];
        else if (tid < 96) vec[V_B2S + tid - 32] = b2[tid - 32];
    }
    __syncthreads();   // XQ zero must complete before interior staging
    if ((int)blockIdx.x < B_SAMPLES) stage_xq(smc, tid, x, blockIdx.x);
    __syncthreads();

    const int r8    = lane & 7;
    const int msel  = (lane >> 3) & 1;
    const int khsel = lane >> 4;
    const int mt2   = wrp & 15;
    const int nh    = wrp >> 4;
    const int stride = gridDim.x;
    const int ox2   = msel * 8 + r8;

    for (int s = blockIdx.x; s < B_SAMPLES; s += stride) {
        // =================================================================
        // conv1 GEMM: D1[1024][32], K=80. Warp w: m-tiles {2w, 2w+1}.
        // =================================================================
        float acc1[2][4][4];
        #pragma unroll
        for (int mt = 0; mt < 2; mt++)
            #pragma unroll
            for (int nt = 0; nt < 4; nt++)
                #pragma unroll
                for (int rg = 0; rg < 4; rg++) acc1[mt][nt][rg] = 0.f;
        {
            #pragma unroll
            for (int ks = 0; ks < 5; ks++) {
                uint32_t bf[2][4];
                uint32_t bb = smaddr + B1_OFF + (uint32_t)(ks * 16 + (lane & 15)) * 80u
                              + (uint32_t)(lane >> 4) * 16u;
                ldsm_x4_t(bf[0], bb);
                ldsm_x4_t(bf[1], bb + 32u);

                const int ta = 2 * ks, tb = 2 * ks + 1;
                const int kya = ta / 3, kxa = ta - 3 * kya;
                const int kyb = (tb < 9) ? tb / 3 : 0, kxb = (tb < 9) ? tb - 3 * kyb : 0;
                uint32_t af[2][4];
                #pragma unroll
                for (int mt = 0; mt < 2; mt++) {
                    int pos = (wrp * 2 + mt) * 16 + msel * 8 + r8;
                    int oy1 = pos >> 5, ox1 = pos & 31;
                    uint32_t addr_e = XQ_OFF + (uint32_t)((kya & 1) * 2 + (kxa & 1)) * XQ_REG
                        + (uint32_t)((oy1 + (kya >> 1)) * 33 + ox1 + (kxa >> 1)) * 16u;
                    uint32_t addr_o = (tb < 9)
                        ? XQ_OFF + (uint32_t)((kyb & 1) * 2 + (kxb & 1)) * XQ_REG
                          + (uint32_t)((oy1 + (kyb >> 1)) * 33 + ox1 + (kxb >> 1)) * 16u
                        : XQ_OFF;                       // zeroed halo slot
                    ldsm_x4(af[mt], smaddr + (khsel ? addr_o : addr_e));
                }
                #pragma unroll
                for (int mt = 0; mt < 2; mt++)
                    #pragma unroll
                    for (int nt = 0; nt < 4; nt++)
                        mma16816(acc1[mt][nt], af[mt], &bf[nt >> 1][(nt & 1) * 2]);
            }
        }
        // ---- writeback: relu(acc1 + b1) -> P ----
        {
            #pragma unroll
            for (int nt = 0; nt < 4; nt++) {
                int n = nt * 8 + (lane & 3) * 2;
                float bb0 = vec[V_B1S + n], bb1 = vec[V_B1S + n + 1];
                uint32_t greg = (uint32_t)(n >> 3) * P_REG;
                uint32_t sub  = (uint32_t)(n & 7) * 2u;
                #pragma unroll
                for (int mt = 0; mt < 2; mt++) {
                    #pragma unroll
                    for (int hh = 0; hh < 2; hh++) {
                        int pos = (wrp * 2 + mt) * 16 + (lane >> 2) + hh * 8;
                        int Y = (pos >> 5) + 1, X = (pos & 31) + 1;
                        float v0 = fmaxf(acc1[mt][nt][hh * 2 + 0] + bb0, 0.f);
                        float v1 = fmaxf(acc1[mt][nt][hh * 2 + 1] + bb1, 0.f);
                        uint32_t off = P_OFF + (uint32_t)((Y & 1) * 2 + (X & 1)) * (4u * P_REG)
                            + greg + (uint32_t)((Y >> 1) * 17 + (X >> 1)) * 16u + sub;
                        *(uint32_t*)(smc + off) = pack_bf16x2(v0, v1);
                    }
                }
            }
        }
        __syncthreads();   // A: P ready; conv1's XQ reads done

        // ---- stage next sample's XQ (overlaps with conv2 below) ----
        int sn = s + stride;
        if (sn < B_SAMPLES) stage_xq(smc, tid, x, sn);

        // =================================================================
        // conv2 GEMM: D2[256][64]. Warp w: m-tile (w&15), n-half (w>>4).
        // 18 stages (tap x gh), DEPTH-2 software pipeline (3 frag buffers).
        // =================================================================
        float acc2[4][4];
        {
            #pragma unroll
            for (int jl = 0; jl < 4; jl++) {
                int oc = nh * 32 + jl * 8 + (lane & 3) * 2;
                float b0  = vec[V_B2S + oc];
                float b1v = vec[V_B2S + oc + 1];
                acc2[jl][0] = b0;  acc2[jl][1] = b1v;
                acc2[jl][2] = b0;  acc2[jl][3] = b1v;
            }
        }
        {
            uint32_t af[3][4];
            uint32_t bf[3][2][4];

            // fragment loader for stage st = tap*2 + gh
            #define LD_STAGE(st, buf)                                              \
            do {                                                                   \
                const int _tap = (st) >> 1, _gh = (st) & 1;                        \
                const int _ky = _tap / 3, _kx = _tap - 3 * _ky;                    \
                uint32_t _pb = P_OFF                                               \
                    + (uint32_t)((_ky & 1) * 2 + (_kx & 1)) * (4u * P_REG)         \
                    + (uint32_t)khsel * P_REG                                      \
                    + (uint32_t)(ox2 + (_kx >> 1)) * 16u                           \
                    + (uint32_t)((mt2 + (_ky >> 1)) * 17) * 16u                    \
                    + (uint32_t)_gh * (2u * P_REG);                                \
                ldsm_x4(af[buf], smaddr + _pb);                                    \
                uint32_t _bb = smaddr + B2_OFF                                     \
                    + (uint32_t)((_tap * 32 + _gh * 16) + (lane & 15)) * 144u      \
                    + (uint32_t)(lane >> 4) * 16u + (uint32_t)(2 * nh) * 32u;      \
                ldsm_x4_t(bf[buf][0], _bb);                                        \
                ldsm_x4_t(bf[buf][1], _bb + 32u);                                  \
            } while (0)

            LD_STAGE(0, 0);
            LD_STAGE(1, 1);
            #pragma unroll
            for (int st = 0; st < 18; st++) {
                const int cur = st % 3;
                if (st < 16) LD_STAGE(st + 2, (st + 2) % 3);
                #pragma unroll
                for (int jl = 0; jl < 4; jl++)
                    mma16816(acc2[jl], af[cur], &bf[cur][jl >> 1][(jl & 1) * 2]);
            }
            #undef LD_STAGE
        }
        // ---- relu + meanpool partials ----
        {
            #pragma unroll
            for (int jl = 0; jl < 4; jl++) {
                float s0 = fmaxf(acc2[jl][0], 0.f) + fmaxf(acc2[jl][2], 0.f);
                float s1 = fmaxf(acc2[jl][1], 0.f) + fmaxf(acc2[jl][3], 0.f);
                s0 += __shfl_xor_sync(0xffffffffu, s0, 4);
                s1 += __shfl_xor_sync(0xffffffffu, s1, 4);
                s0 += __shfl_xor_sync(0xffffffffu, s0, 8);
                s1 += __shfl_xor_sync(0xffffffffu, s1, 8);
                s0 += __shfl_xor_sync(0xffffffffu, s0, 16);
                s1 += __shfl_xor_sync(0xffffffffu, s1, 16);
                if (lane < 4) {
                    vec[V_PP + wrp * 32 + jl * 8 + lane * 2]     = s0;
                    vec[V_PP + wrp * 32 + jl * 8 + lane * 2 + 1] = s1;
                }
            }
        }
        __syncthreads();   // B: PP ready; XQ(sn) staged for next conv1

        if (tid < 64) {
            int nhh = tid >> 5, oc32 = tid & 31;
            float sacc = 0.f;
            #pragma unroll
            for (int mp = 0; mp < 16; mp++)
                sacc += vec[V_PP + (nhh * 16 + mp) * 32 + oc32];
            g_pool[s * 64 + nhh * 32 + oc32] = sacc * (1.f / 256.f);
        }
        // PP reads finish before any warp passes next iteration's sync A,
        // which precedes the next conv2's PP writes — no extra barrier needed.
    }
}

// ===========================================================================
// K2: warp-per-sample MLP + C matvec + softmax. No smem, no barriers.
// ===========================================================================
__global__ __launch_bounds__(256, 4)
void gcp_mlp_kernel(const float* __restrict__ C,
                    const float* __restrict__ encw, const float* __restrict__ encb,
                    const float* __restrict__ f1w,  const float* __restrict__ f1b,
                    const float* __restrict__ f2w,  const float* __restrict__ f2b,
                    const float* __restrict__ f3w,  const float* __restrict__ f3b,
                    const float* __restrict__ f4w,  const float* __restrict__ f4b,
                    const float* __restrict__ f5w,  const float* __restrict__ f5b,
                    const float* __restrict__ ow,   const float* __restrict__ ob,
                    float* __restrict__ out)
{
    const int s    = blockIdx.x * 8 + (threadIdx.x >> 5);
    const int lane = threadIdx.x & 31;
    const unsigned FULL = 0xffffffffu;

    const float p0 = g_pool[s * 64 + lane];
    const float p1 = g_pool[s * 64 + 32 + lane];

    float x1r[4];
    #pragma unroll
    for (int j = 0; j < 4; j++) x1r[j] = encb[lane + 32 * j];
    #pragma unroll 4
    for (int k = 0; k < 64; k++) {
        float v = (k < 32) ? __shfl_sync(FULL, p0, k) : __shfl_sync(FULL, p1, k - 32);
        #pragma unroll
        for (int j = 0; j < 4; j++)
            x1r[j] = fmaf(v, __ldg(&encw[k * 128 + lane + 32 * j]), x1r[j]);
    }
    #pragma unroll
    for (int j = 0; j < 4; j++) x1r[j] = fmaxf(x1r[j], 0.f);

    float a0 = f1b[lane];
    float a1 = (lane < 18) ? f1b[lane + 32] : 0.f;
    const int nc = (lane < 18) ? lane + 32 : 49;
    #pragma unroll 4
    for (int k = 0; k < 128; k++) {
        float v = __shfl_sync(FULL, x1r[k >> 5], k & 31);
        a0 = fmaf(v, __ldg(&f1w[k * NVAR + lane]), a0);
        a1 = fmaf(v, __ldg(&f1w[k * NVAR + nc]), a1);
    }
    float x2a = fmaxf(a0, 0.f);
    float x2b = fmaxf(a1, 0.f);

    float ea = 0.f, eb = 0.f;
    {
        const float* cs = C + (size_t)s * 2500;
        for (int n = 0; n < NVAR; n++) {
            float t = __ldg(&cs[n * NVAR + lane]) * x2a;
            if (lane < 18) t = fmaf(__ldg(&cs[n * NVAR + 32 + lane]), x2b, t);
            #pragma unroll
            for (int off = 16; off > 0; off >>= 1)
                t += __shfl_xor_sync(FULL, t, off);
            if (n < 32) { if (lane == n) ea = t; }
            else        { if (lane == n - 32) eb = t; }
        }
    }

    float x3r[4];
    #pragma unroll
    for (int j = 0; j < 4; j++) x3r[j] = f2b[lane + 32 * j];
    #pragma unroll 2
    for (int k = 0; k < NVAR; k++) {
        float v = (k < 32) ? __shfl_sync(FULL, ea, k) : __shfl_sync(FULL, eb, k - 32);
        #pragma unroll
        for (int j = 0; j < 4; j++)
            x3r[j] = fmaf(v, __ldg(&f2w[k * 128 + lane + 32 * j]), x3r[j]);
    }
    #pragma unroll
    for (int j = 0; j < 4; j++) x3r[j] = fmaxf(x3r[j], 0.f);

    float b0 = f3b[lane], b1v = f3b[lane + 32];
    #pragma unroll 4
    for (int k = 0; k < 256; k++) {
        float v = (k < 128) ? __shfl_sync(FULL, x1r[k >> 5], k & 31)
                            : __shfl_sync(FULL, x3r[(k - 128) >> 5], (k - 128) & 31);
        b0  = fmaf(v, __ldg(&f3w[k * 64 + lane]), b0);
        b1v = fmaf(v, __ldg(&f3w[k * 64 + lane + 32]), b1v);
    }
    float x5a = fmaxf(b0, 0.f), x5b = fmaxf(b1v, 0.f);

    float c0 = f4b[lane], c1 = f4b[lane + 32];
    #pragma unroll 4
    for (int k = 0; k < 64; k++) {
        float v = (k < 32) ? __shfl_sync(FULL, x5a, k) : __shfl_sync(FULL, x5b, k - 32);
        c0 = fmaf(v, __ldg(&f4w[k * 64 + lane]), c0);
        c1 = fmaf(v, __ldg(&f4w[k * 64 + lane + 32]), c1);
    }
    float x6a = fmaxf(c0, 0.f), x6b = fmaxf(c1, 0.f);

    float d0 = f5b[lane], d1 = f5b[lane + 32];
    #pragma unroll 4
    for (int k = 0; k < 64; k++) {
        float v = (k < 32) ? __shfl_sync(FULL, x6a, k) : __shfl_sync(FULL, x6b, k - 32);
        d0 = fmaf(v, __ldg(&f5w[k * 64 + lane]), d0);
        d1 = fmaf(v, __ldg(&f5w[k * 64 + lane + 32]), d1);
    }
    float x7a = fmaxf(d0, 0.f), x7b = fmaxf(d1, 0.f);

    float l0 = ob[lane];
    float l1 = (lane < 18) ? ob[lane + 32] : 0.f;
    #pragma unroll 4
    for (int k = 0; k < 64; k++) {
        float v = (k < 32) ? __shfl_sync(FULL, x7a, k) : __shfl_sync(FULL, x7b, k - 32);
        l0 = fmaf(v, __ldg(&ow[k * NVAR + lane]), l0);
        l1 = fmaf(v, __ldg(&ow[k * NVAR + nc]), l1);
    }
    l0 = fmaxf(l0, 0.f);
    l1 = (lane < 18) ? fmaxf(l1, 0.f) : -1e30f;

    float m = fmaxf(l0, l1);
    #pragma unroll
    for (int off = 16; off > 0; off >>= 1)
        m = fmaxf(m, __shfl_xor_sync(FULL, m, off));
    float e0 = expf(l0 - m);
    float e1 = (lane < 18) ? expf(l1 - m) : 0.f;
    float ssum = e0 + e1;
    #pragma unroll
    for (int off = 16; off > 0; off >>= 1)
        ssum += __shfl_xor_sync(FULL, ssum, off);
    float inv = 1.f / ssum;
    out[s * NVAR + lane] = e0 * inv;
    if (lane < 18) out[s * NVAR + 32 + lane] = e1 * inv;
}

extern "C" void kernel_launch(void* const* d_in, const int* in_sizes, int n_in,
                              void* d_out, int out_size)
{
    (void)in_sizes; (void)n_in; (void)out_size;
    const float* x    = (const float*)d_in[0];
    const float* C    = (const float*)d_in[1];
    const float* w1   = (const float*)d_in[2];
    const float* b1   = (const float*)d_in[3];
    const float* w2   = (const float*)d_in[4];
    const float* b2   = (const float*)d_in[5];
    const float* encw = (const float*)d_in[6];
    const float* encb = (const float*)d_in[7];
    const float* f1w  = (const float*)d_in[8];
    const float* f1b  = (const float*)d_in[9];
    const float* f2w  = (const float*)d_in[10];
    const float* f2b  = (const float*)d_in[11];
    const float* f3w  = (const float*)d_in[12];
    const float* f3b  = (const float*)d_in[13];
    const float* f4w  = (const float*)d_in[14];
    const float* f4b  = (const float*)d_in[15];
    const float* f5w  = (const float*)d_in[16];
    const float* f5b  = (const float*)d_in[17];
    const float* ow   = (const float*)d_in[18];
    const float* ob   = (const float*)d_in[19];
    float* out = (float*)d_out;

    int nsm = 148;
    cudaDeviceGetAttribute(&nsm, cudaDevAttrMultiProcessorCount, 0);

    w_prep_kernel<<<94, 256>>>(w1, w2);

    cudaFuncSetAttribute(gcp_conv_kernel,
                         cudaFuncAttributeMaxDynamicSharedMemorySize, SMEM_BYTES);
    gcp_conv_kernel<<<nsm, NTHREADS, SMEM_BYTES>>>(x, b1, b2);

    gcp_mlp_kernel<<<B_SAMPLES / 8, 256>>>(C, encw, encb, f1w, f1b, f2w, f2b,
                                           f3w, f3b, f4w, f4b, f5w, f5b, ow, ob, out);
}

// round 13
// speedup vs baseline: 1.0189x; 1.0189x over previous
#include <cuda_runtime.h>
#include <cuda_bf16.h>
#include <cstdint>

// ===========================================================================
// Goal_Conditioned_Policies forward, persistent-CTA conv + warp-per-sample MLP.
// K1: one CTA per SM (1024 thr), grid-strides over samples.
//     conv1: 32 warps (2 m-tiles each). conv2: WARP-SPECIALIZED —
//     warps 0-15 run GEMM with fat 2m x 4n tiles (-33% ldsm traffic),
//     warps 16-31 stage the next sample's input concurrently.
// K2: warp-per-sample MLP + C matvec + softmax in registers via shfl.
// ===========================================================================

#define NTHREADS  1024
#define NVAR      50
#define B_SAMPLES 4096

// ---- K1 smem byte offsets ----
#define XQ_OFF   0u            // [4 pyx][33][33][16B] = 69,696
#define P_OFF    69696u        // [4 pyx][4 g][17][17][16B] = 73,984
#define B1_OFF   143680u       // conv1 weights [80 k][80 B rows] = 6,400
#define B2_OFF   150080u       // conv2 weights [288 k][144 B rows] = 41,472
#define VEC_OFF  191552u
#define SMEM_BYTES 196096u

#define XQ_REG 17424u          // 33*33*16
#define P_REG  4624u           // 17*17*16

// vec float indices
#define V_B1S  0
#define V_B2S  32
#define V_PP   96        // pool partials [16 conv2-warps][32]

__device__ __forceinline__ uint32_t smem_u32(const void* p) {
    uint32_t a;
    asm("{ .reg .u64 t; cvta.to.shared.u64 t, %1; cvt.u32.u64 %0, t; }" : "=r"(a) : "l"(p));
    return a;
}
__device__ __forceinline__ void ldsm_x4(uint32_t* r, uint32_t addr) {
    asm volatile("ldmatrix.sync.aligned.m8n8.x4.shared.b16 {%0,%1,%2,%3}, [%4];"
        : "=r"(r[0]), "=r"(r[1]), "=r"(r[2]), "=r"(r[3]) : "r"(addr));
}
__device__ __forceinline__ void ldsm_x4_t(uint32_t* r, uint32_t addr) {
    asm volatile("ldmatrix.sync.aligned.m8n8.x4.trans.shared.b16 {%0,%1,%2,%3}, [%4];"
        : "=r"(r[0]), "=r"(r[1]), "=r"(r[2]), "=r"(r[3]) : "r"(addr));
}
__device__ __forceinline__ void mma16816(float* d, const uint32_t* a, const uint32_t* b) {
    asm volatile(
        "mma.sync.aligned.m16n8k16.row.col.f32.bf16.bf16.f32 "
        "{%0,%1,%2,%3}, {%4,%5,%6,%7}, {%8,%9}, {%0,%1,%2,%3};"
        : "+f"(d[0]), "+f"(d[1]), "+f"(d[2]), "+f"(d[3])
        : "r"(a[0]), "r"(a[1]), "r"(a[2]), "r"(a[3]), "r"(b[0]), "r"(b[1]));
}
__device__ __forceinline__ uint32_t pack_bf16x2(float lo, float hi) {
    uint32_t r;
    asm("cvt.rn.bf16x2.f32 %0, %1, %2;" : "=r"(r) : "f"(hi), "f"(lo));
    return r;
}

// --- global scratch (static device arrays; rebuilt deterministically) ---
__device__ __align__(16) __nv_bfloat16 g_B1[80 * 40];
__device__ __align__(16) __nv_bfloat16 g_B2[288 * 72];
__device__ __align__(16) float g_pool[B_SAMPLES * 64];

__global__ void w_prep_kernel(const float* __restrict__ w1, const float* __restrict__ w2) {
    int i = blockIdx.x * blockDim.x + threadIdx.x;
    if (i < 80 * 40) {
        int kk = i / 40, slot = i - kk * 40;
        int tap = kk >> 3, j = kk & 7;
        float v = 0.f;
        if (slot < 32 && j < 3 && kk < 72)
            v = w1[slot * 27 + j * 9 + tap];    // w1[oc][ic=j][tap]
        g_B1[i] = __float2bfloat16(v);
    }
    int i2 = i - 80 * 40;
    if (i2 >= 0 && i2 < 288 * 72) {
        int kk = i2 / 72, slot = i2 - kk * 72;
        int tap = kk >> 5, ic = kk & 31;
        float v = (slot < 64) ? w2[(slot * 32 + ic) * 9 + tap] : 0.f;
        g_B2[i2] = __float2bfloat16(v);
    }
}

// Stage a sample's x into XQ with NT threads (t in [0, NT)); lower 8B of each
// interior pixel cell; upper 8B zeroed once at setup, never overwritten.
template<int NT>
__device__ __forceinline__ void stage_xq_n(char* smc, int t, const float* __restrict__ x, int s) {
    const float* xb = x + (size_t)s * 12288;
    #pragma unroll
    for (int it = 0; it < 4096 / NT; it++) {
        int i = it * NT + t;                    // pixel index 0..4095
        float v0 = xb[i];
        float v1 = xb[4096 + i];
        float v2 = xb[8192 + i];
        uint2 q;
        q.x = pack_bf16x2(v0, v1);
        q.y = pack_bf16x2(v2, 0.f);
        int Y = (i >> 6) + 1, X = (i & 63) + 1;
        uint32_t off = XQ_OFF + (uint32_t)((Y & 1) * 2 + (X & 1)) * XQ_REG
                     + (uint32_t)((Y >> 1) * 33 + (X >> 1)) * 16u;
        *(uint2*)(smc + off) = q;
    }
}

// ===========================================================================
// K1: persistent convs + pool (1024 threads, 32 warps, 1 CTA/SM)
// ===========================================================================
__global__ __launch_bounds__(NTHREADS, 1)
void gcp_conv_kernel(const float* __restrict__ x,
                     const float* __restrict__ b1, const float* __restrict__ b2)
{
    extern __shared__ char smc[];
    const uint32_t smaddr = smem_u32(smc);
    const int tid  = threadIdx.x;
    const int wrp  = tid >> 5;
    const int lane = tid & 31;
    float* vec = (float*)(smc + VEC_OFF);

    // ---- one-time setup: zero FULL XQ (pads + halos), P halos, B1/B2, biases ----
    {
        uint4 z = make_uint4(0, 0, 0, 0);
        for (int i = tid; i < 4356; i += NTHREADS)      // all of XQ (69,696 B)
            ((uint4*)(smc + XQ_OFF))[i] = z;
        for (int i = tid; i < 544; i += NTHREADS) {
            int c = i / 34, r = i - c * 34;
            int pyx = c >> 2, g = c & 3;
            int py = pyx >> 1, px = pyx & 1;
            int iy_h = (py == 0) ? 0 : 16;
            int ix_h = (px == 0) ? 0 : 16;
            int iy, ix;
            if (r < 17) { iy = iy_h; ix = r; }
            else        { iy = r - 17; ix = ix_h; }
            *(uint4*)(smc + P_OFF + (uint32_t)(pyx * 4 + g) * P_REG
                      + (uint32_t)(iy * 17 + ix) * 16u) = z;
        }
        const uint4* gb1 = (const uint4*)g_B1;
        for (int i = tid; i < 400; i += NTHREADS)
            ((uint4*)(smc + B1_OFF))[i] = gb1[i];
        const uint4* gb2 = (const uint4*)g_B2;
        for (int i = tid; i < 2592; i += NTHREADS)
            ((uint4*)(smc + B2_OFF))[i] = gb2[i];
        if (tid < 32) vec[V_B1S + tid] = b1[tid];
        else if (tid < 96) vec[V_B2S + tid - 32] = b2[tid - 32];
    }
    __syncthreads();   // XQ zero must complete before interior staging
    if ((int)blockIdx.x < B_SAMPLES) stage_xq_n<NTHREADS>(smc, tid, x, blockIdx.x);
    __syncthreads();

    const int r8    = lane & 7;
    const int msel  = (lane >> 3) & 1;
    const int khsel = lane >> 4;
    const int stride = gridDim.x;
    const int ox2   = msel * 8 + r8;

    for (int s = blockIdx.x; s < B_SAMPLES; s += stride) {
        // =================================================================
        // conv1 GEMM: D1[1024][32], K=80. All 32 warps, m-tiles {2w, 2w+1}.
        // =================================================================
        float acc1[2][4][4];
        #pragma unroll
        for (int mt = 0; mt < 2; mt++)
            #pragma unroll
            for (int nt = 0; nt < 4; nt++)
                #pragma unroll
                for (int rg = 0; rg < 4; rg++) acc1[mt][nt][rg] = 0.f;
        {
            #pragma unroll
            for (int ks = 0; ks < 5; ks++) {
                uint32_t bf[2][4];
                uint32_t bb = smaddr + B1_OFF + (uint32_t)(ks * 16 + (lane & 15)) * 80u
                              + (uint32_t)(lane >> 4) * 16u;
                ldsm_x4_t(bf[0], bb);
                ldsm_x4_t(bf[1], bb + 32u);

                const int ta = 2 * ks, tb = 2 * ks + 1;
                const int kya = ta / 3, kxa = ta - 3 * kya;
                const int kyb = (tb < 9) ? tb / 3 : 0, kxb = (tb < 9) ? tb - 3 * kyb : 0;
                uint32_t af[2][4];
                #pragma unroll
                for (int mt = 0; mt < 2; mt++) {
                    int pos = (wrp * 2 + mt) * 16 + msel * 8 + r8;
                    int oy1 = pos >> 5, ox1 = pos & 31;
                    uint32_t addr_e = XQ_OFF + (uint32_t)((kya & 1) * 2 + (kxa & 1)) * XQ_REG
                        + (uint32_t)((oy1 + (kya >> 1)) * 33 + ox1 + (kxa >> 1)) * 16u;
                    uint32_t addr_o = (tb < 9)
                        ? XQ_OFF + (uint32_t)((kyb & 1) * 2 + (kxb & 1)) * XQ_REG
                          + (uint32_t)((oy1 + (kyb >> 1)) * 33 + ox1 + (kxb >> 1)) * 16u
                        : XQ_OFF;                       // zeroed halo slot
                    ldsm_x4(af[mt], smaddr + (khsel ? addr_o : addr_e));
                }
                #pragma unroll
                for (int mt = 0; mt < 2; mt++)
                    #pragma unroll
                    for (int nt = 0; nt < 4; nt++)
                        mma16816(acc1[mt][nt], af[mt], &bf[nt >> 1][(nt & 1) * 2]);
            }
        }
        // ---- writeback: relu(acc1 + b1) -> P ----
        {
            #pragma unroll
            for (int nt = 0; nt < 4; nt++) {
                int n = nt * 8 + (lane & 3) * 2;
                float bb0 = vec[V_B1S + n], bb1 = vec[V_B1S + n + 1];
                uint32_t greg = (uint32_t)(n >> 3) * P_REG;
                uint32_t sub  = (uint32_t)(n & 7) * 2u;
                #pragma unroll
                for (int mt = 0; mt < 2; mt++) {
                    #pragma unroll
                    for (int hh = 0; hh < 2; hh++) {
                        int pos = (wrp * 2 + mt) * 16 + (lane >> 2) + hh * 8;
                        int Y = (pos >> 5) + 1, X = (pos & 31) + 1;
                        float v0 = fmaxf(acc1[mt][nt][hh * 2 + 0] + bb0, 0.f);
                        float v1 = fmaxf(acc1[mt][nt][hh * 2 + 1] + bb1, 0.f);
                        uint32_t off = P_OFF + (uint32_t)((Y & 1) * 2 + (X & 1)) * (4u * P_REG)
                            + greg + (uint32_t)((Y >> 1) * 17 + (X >> 1)) * 16u + sub;
                        *(uint32_t*)(smc + off) = pack_bf16x2(v0, v1);
                    }
                }
            }
        }
        __syncthreads();   // A: P ready; conv1's XQ reads done

        int sn = s + stride;
        if (wrp >= 16) {
            // ---- copy warps: stage next sample's XQ during conv2 ----
            if (sn < B_SAMPLES) stage_xq_n<512>(smc, tid - 512, x, sn);
        } else {
            // =============================================================
            // conv2 GEMM: D2[256][64]. 16 warps, fat tiles:
            // warp w: m-tiles {2(w&7), 2(w&7)+1}, n-half (w>>3).
            // =============================================================
            const int mt0 = (wrp & 7) * 2;
            const int nh  = wrp >> 3;
            float acc2[2][4][4];
            #pragma unroll
            for (int jl = 0; jl < 4; jl++) {
                int oc = nh * 32 + jl * 8 + (lane & 3) * 2;
                float b0  = vec[V_B2S + oc];
                float b1v = vec[V_B2S + oc + 1];
                #pragma unroll
                for (int mt = 0; mt < 2; mt++) {
                    acc2[mt][jl][0] = b0;  acc2[mt][jl][1] = b1v;
                    acc2[mt][jl][2] = b0;  acc2[mt][jl][3] = b1v;
                }
            }
            #pragma unroll
            for (int tap = 0; tap < 9; tap++) {
                const int ky = tap / 3, kx = tap - 3 * ky;
                const uint32_t pbase = P_OFF
                    + (uint32_t)((ky & 1) * 2 + (kx & 1)) * (4u * P_REG)
                    + (uint32_t)khsel * P_REG + (uint32_t)(ox2 + (kx >> 1)) * 16u;
                #pragma unroll
                for (int gh = 0; gh < 2; gh++) {
                    uint32_t af[2][4];
                    #pragma unroll
                    for (int mt = 0; mt < 2; mt++) {
                        uint32_t ra = pbase + (uint32_t)gh * (2u * P_REG)
                            + (uint32_t)((mt0 + mt + (ky >> 1)) * 17) * 16u;
                        ldsm_x4(af[mt], smaddr + ra);
                    }
                    uint32_t bf[2][4];
                    uint32_t bb = smaddr + B2_OFF
                        + (uint32_t)((tap * 32 + gh * 16) + (lane & 15)) * 144u
                        + (uint32_t)(lane >> 4) * 16u + (uint32_t)(2 * nh) * 32u;
                    ldsm_x4_t(bf[0], bb);
                    ldsm_x4_t(bf[1], bb + 32u);
                    #pragma unroll
                    for (int mt = 0; mt < 2; mt++)
                        #pragma unroll
                        for (int jl = 0; jl < 4; jl++)
                            mma16816(acc2[mt][jl], af[mt], &bf[jl >> 1][(jl & 1) * 2]);
                }
            }
            // ---- relu + meanpool partials (over this warp's 2 m-tiles) ----
            #pragma unroll
            for (int jl = 0; jl < 4; jl++) {
                float s0 = 0.f, s1 = 0.f;
                #pragma unroll
                for (int mt = 0; mt < 2; mt++) {
                    s0 += fmaxf(acc2[mt][jl][0], 0.f) + fmaxf(acc2[mt][jl][2], 0.f);
                    s1 += fmaxf(acc2[mt][jl][1], 0.f) + fmaxf(acc2[mt][jl][3], 0.f);
                }
                s0 += __shfl_xor_sync(0xffffffffu, s0, 4);
                s1 += __shfl_xor_sync(0xffffffffu, s1, 4);
                s0 += __shfl_xor_sync(0xffffffffu, s0, 8);
                s1 += __shfl_xor_sync(0xffffffffu, s1, 8);
                s0 += __shfl_xor_sync(0xffffffffu, s0, 16);
                s1 += __shfl_xor_sync(0xffffffffu, s1, 16);
                if (lane < 4) {
                    vec[V_PP + wrp * 32 + jl * 8 + lane * 2]     = s0;
                    vec[V_PP + wrp * 32 + jl * 8 + lane * 2 + 1] = s1;
                }
            }
        }
        __syncthreads();   // B: PP ready; XQ(sn) staged for next conv1

        if (tid < 64) {
            int nhh = tid >> 5, oc32 = tid & 31;
            float sacc = 0.f;
            #pragma unroll
            for (int mp = 0; mp < 8; mp++)
                sacc += vec[V_PP + (nhh * 8 + mp) * 32 + oc32];
            g_pool[s * 64 + nhh * 32 + oc32] = sacc * (1.f / 256.f);
        }
        // PP reads finish before any warp passes next iteration's sync A,
        // which precedes the next conv2's PP writes — no extra barrier needed.
    }
}

// ===========================================================================
// K2: warp-per-sample MLP + C matvec + softmax. No smem, no barriers.
// ===========================================================================
__global__ __launch_bounds__(256, 4)
void gcp_mlp_kernel(const float* __restrict__ C,
                    const float* __restrict__ encw, const float* __restrict__ encb,
                    const float* __restrict__ f1w,  const float* __restrict__ f1b,
                    const float* __restrict__ f2w,  const float* __restrict__ f2b,
                    const float* __restrict__ f3w,  const float* __restrict__ f3b,
                    const float* __restrict__ f4w,  const float* __restrict__ f4b,
                    const float* __restrict__ f5w,  const float* __restrict__ f5b,
                    const float* __restrict__ ow,   const float* __restrict__ ob,
                    float* __restrict__ out)
{
    const int s    = blockIdx.x * 8 + (threadIdx.x >> 5);
    const int lane = threadIdx.x & 31;
    const unsigned FULL = 0xffffffffu;

    const float p0 = g_pool[s * 64 + lane];
    const float p1 = g_pool[s * 64 + 32 + lane];

    float x1r[4];
    #pragma unroll
    for (int j = 0; j < 4; j++) x1r[j] = encb[lane + 32 * j];
    #pragma unroll 4
    for (int k = 0; k < 64; k++) {
        float v = (k < 32) ? __shfl_sync(FULL, p0, k) : __shfl_sync(FULL, p1, k - 32);
        #pragma unroll
        for (int j = 0; j < 4; j++)
            x1r[j] = fmaf(v, __ldg(&encw[k * 128 + lane + 32 * j]), x1r[j]);
    }
    #pragma unroll
    for (int j = 0; j < 4; j++) x1r[j] = fmaxf(x1r[j], 0.f);

    float a0 = f1b[lane];
    float a1 = (lane < 18) ? f1b[lane + 32] : 0.f;
    const int nc = (lane < 18) ? lane + 32 : 49;
    #pragma unroll 4
    for (int k = 0; k < 128; k++) {
        float v = __shfl_sync(FULL, x1r[k >> 5], k & 31);
        a0 = fmaf(v, __ldg(&f1w[k * NVAR + lane]), a0);
        a1 = fmaf(v, __ldg(&f1w[k * NVAR + nc]), a1);
    }
    float x2a = fmaxf(a0, 0.f);
    float x2b = fmaxf(a1, 0.f);

    float ea = 0.f, eb = 0.f;
    {
        const float* cs = C + (size_t)s * 2500;
        for (int n = 0; n < NVAR; n++) {
            float t = __ldg(&cs[n * NVAR + lane]) * x2a;
            if (lane < 18) t = fmaf(__ldg(&cs[n * NVAR + 32 + lane]), x2b, t);
            #pragma unroll
            for (int off = 16; off > 0; off >>= 1)
                t += __shfl_xor_sync(FULL, t, off);
            if (n < 32) { if (lane == n) ea = t; }
            else        { if (lane == n - 32) eb = t; }
        }
    }

    float x3r[4];
    #pragma unroll
    for (int j = 0; j < 4; j++) x3r[j] = f2b[lane + 32 * j];
    #pragma unroll 2
    for (int k = 0; k < NVAR; k++) {
        float v = (k < 32) ? __shfl_sync(FULL, ea, k) : __shfl_sync(FULL, eb, k - 32);
        #pragma unroll
        for (int j = 0; j < 4; j++)
            x3r[j] = fmaf(v, __ldg(&f2w[k * 128 + lane + 32 * j]), x3r[j]);
    }
    #pragma unroll
    for (int j = 0; j < 4; j++) x3r[j] = fmaxf(x3r[j], 0.f);

    float b0 = f3b[lane], b1v = f3b[lane + 32];
    #pragma unroll 4
    for (int k = 0; k < 256; k++) {
        float v = (k < 128) ? __shfl_sync(FULL, x1r[k >> 5], k & 31)
                            : __shfl_sync(FULL, x3r[(k - 128) >> 5], (k - 128) & 31);
        b0  = fmaf(v, __ldg(&f3w[k * 64 + lane]), b0);
        b1v = fmaf(v, __ldg(&f3w[k * 64 + lane + 32]), b1v);
    }
    float x5a = fmaxf(b0, 0.f), x5b = fmaxf(b1v, 0.f);

    float c0 = f4b[lane], c1 = f4b[lane + 32];
    #pragma unroll 4
    for (int k = 0; k < 64; k++) {
        float v = (k < 32) ? __shfl_sync(FULL, x5a, k) : __shfl_sync(FULL, x5b, k - 32);
        c0 = fmaf(v, __ldg(&f4w[k * 64 + lane]), c0);
        c1 = fmaf(v, __ldg(&f4w[k * 64 + lane + 32]), c1);
    }
    float x6a = fmaxf(c0, 0.f), x6b = fmaxf(c1, 0.f);

    float d0 = f5b[lane], d1 = f5b[lane + 32];
    #pragma unroll 4
    for (int k = 0; k < 64; k++) {
        float v = (k < 32) ? __shfl_sync(FULL, x6a, k) : __shfl_sync(FULL, x6b, k - 32);
        d0 = fmaf(v, __ldg(&f5w[k * 64 + lane]), d0);
        d1 = fmaf(v, __ldg(&f5w[k * 64 + lane + 32]), d1);
    }
    float x7a = fmaxf(d0, 0.f), x7b = fmaxf(d1, 0.f);

    float l0 = ob[lane];
    float l1 = (lane < 18) ? ob[lane + 32] : 0.f;
    #pragma unroll 4
    for (int k = 0; k < 64; k++) {
        float v = (k < 32) ? __shfl_sync(FULL, x7a, k) : __shfl_sync(FULL, x7b, k - 32);
        l0 = fmaf(v, __ldg(&ow[k * NVAR + lane]), l0);
        l1 = fmaf(v, __ldg(&ow[k * NVAR + nc]), l1);
    }
    l0 = fmaxf(l0, 0.f);
    l1 = (lane < 18) ? fmaxf(l1, 0.f) : -1e30f;

    float m = fmaxf(l0, l1);
    #pragma unroll
    for (int off = 16; off > 0; off >>= 1)
        m = fmaxf(m, __shfl_xor_sync(FULL, m, off));
    float e0 = expf(l0 - m);
    float e1 = (lane < 18) ? expf(l1 - m) : 0.f;
    float ssum = e0 + e1;
    #pragma unroll
    for (int off = 16; off > 0; off >>= 1)
        ssum += __shfl_xor_sync(FULL, ssum, off);
    float inv = 1.f / ssum;
    out[s * NVAR + lane] = e0 * inv;
    if (lane < 18) out[s * NVAR + 32 + lane] = e1 * inv;
}

extern "C" void kernel_launch(void* const* d_in, const int* in_sizes, int n_in,
                              void* d_out, int out_size)
{
    (void)in_sizes; (void)n_in; (void)out_size;
    const float* x    = (const float*)d_in[0];
    const float* C    = (const float*)d_in[1];
    const float* w1   = (const float*)d_in[2];
    const float* b1   = (const float*)d_in[3];
    const float* w2   = (const float*)d_in[4];
    const float* b2   = (const float*)d_in[5];
    const float* encw = (const float*)d_in[6];
    const float* encb = (const float*)d_in[7];
    const float* f1w  = (const float*)d_in[8];
    const float* f1b  = (const float*)d_in[9];
    const float* f2w  = (const float*)d_in[10];
    const float* f2b  = (const float*)d_in[11];
    const float* f3w  = (const float*)d_in[12];
    const float* f3b  = (const float*)d_in[13];
    const float* f4w  = (const float*)d_in[14];
    const float* f4b  = (const float*)d_in[15];
    const float* f5w  = (const float*)d_in[16];
    const float* f5b  = (const float*)d_in[17];
    const float* ow   = (const float*)d_in[18];
    const float* ob   = (const float*)d_in[19];
    float* out = (float*)d_out;

    int nsm = 148;
    cudaDeviceGetAttribute(&nsm, cudaDevAttrMultiProcessorCount, 0);

    w_prep_kernel<<<94, 256>>>(w1, w2);

    cudaFuncSetAttribute(gcp_conv_kernel,
                         cudaFuncAttributeMaxDynamicSharedMemorySize, SMEM_BYTES);
    gcp_conv_kernel<<<nsm, NTHREADS, SMEM_BYTES>>>(x, b1, b2);

    gcp_mlp_kernel<<<B_SAMPLES / 8, 256>>>(C, encw, encb, f1w, f1b, f2w, f2b,
                                           f3w, f3b, f4w, f4b, f5w, f5b, ow, ob, out);
}